// round 9
// baseline (speedup 1.0000x reference)
#include <cuda_runtime.h>
#include <cuda_fp16.h>
#include <cstdint>

#define N_NODES 100000
#define N_PAIRS 640000
#define F_TOTAL 128
#define N_HEADS 8
#define HEAD_DIM 16

// projected q in (node, 128) fp32 layout.
// kv in fp16, interleaved per lane: node n, lane l -> uint4 = {k quad, v quad}.
__device__ float g_q[N_NODES * F_TOTAL];
__device__ uint4 g_kv[N_NODES * 32];

// CSR-by-idx_i machinery
__device__ int  g_cnt[N_NODES];      // zeroed inside proj_kernel each call
__device__ int  g_cursor[N_NODES];   // scan1 writes chunk-local exclusive prefix
__device__ int4 g_meta[N_PAIRS];     // {pair_id, idx_j, phi_bits, idx_i} grouped by idx_i
#define NB1 98                        // ceil(100000/1024)
__device__ int g_bsum[NB1];

#define W_STRIDE 260

__global__ void __launch_bounds__(256) proj_kernel(
    const float* __restrict__ x,
    const float* __restrict__ wq,
    const float* __restrict__ wk,
    const float* __restrict__ wv)
{
    __shared__ float sq[N_HEADS * W_STRIDE];
    __shared__ float sk[N_HEADS * W_STRIDE];
    __shared__ float sv[N_HEADS * W_STRIDE];

    int gid = blockIdx.x * 256 + threadIdx.x;   // node*8 + head
    if (gid < N_NODES) g_cnt[gid] = 0;          // fused zero_cnt

    for (int i = threadIdx.x; i < N_HEADS * HEAD_DIM * HEAD_DIM; i += 256) {
        int h = i >> 8;
        int r = i & 255;
        sq[h * W_STRIDE + r] = wq[i];
        sk[h * W_STRIDE + r] = wk[i];
        sv[h * W_STRIDE + r] = wv[i];
    }
    __syncthreads();

    if (gid >= N_NODES * N_HEADS) return;
    int n = gid >> 3;
    int h = gid & 7;

    const float4* xp = reinterpret_cast<const float4*>(x + (size_t)n * F_TOTAL + h * HEAD_DIM);
    float4 xv0 = xp[0], xv1 = xp[1], xv2 = xp[2], xv3 = xp[3];
    float xr[16] = {xv0.x, xv0.y, xv0.z, xv0.w,
                    xv1.x, xv1.y, xv1.z, xv1.w,
                    xv2.x, xv2.y, xv2.z, xv2.w,
                    xv3.x, xv3.y, xv3.z, xv3.w};

    const float4* wq4 = reinterpret_cast<const float4*>(sq + h * W_STRIDE);
    const float4* wk4 = reinterpret_cast<const float4*>(sk + h * W_STRIDE);
    const float4* wv4 = reinterpret_cast<const float4*>(sv + h * W_STRIDE);

    float qo[16], ko[16], vo[16];
#pragma unroll
    for (int e = 0; e < 16; e++) {
        float aq = 0.f, ak = 0.f, av = 0.f;
#pragma unroll
        for (int d4 = 0; d4 < 4; d4++) {
            float4 a = wq4[e * 4 + d4];
            float4 b = wk4[e * 4 + d4];
            float4 c = wv4[e * 4 + d4];
            float x0 = xr[4 * d4 + 0], x1 = xr[4 * d4 + 1];
            float x2 = xr[4 * d4 + 2], x3 = xr[4 * d4 + 3];
            aq += x0 * a.x + x1 * a.y + x2 * a.z + x3 * a.w;
            ak += x0 * b.x + x1 * b.y + x2 * b.z + x3 * b.w;
            av += x0 * c.x + x1 * c.y + x2 * c.z + x3 * c.w;
        }
        qo[e] = aq; ko[e] = ak; vo[e] = av;
    }

    float4* qdst = reinterpret_cast<float4*>(g_q + (size_t)n * F_TOTAL + h * HEAD_DIM);
#pragma unroll
    for (int t = 0; t < 4; t++) {
        qdst[t] = make_float4(qo[4*t], qo[4*t+1], qo[4*t+2], qo[4*t+3]);
        int lane = h * 4 + t;
        half2 k01 = __floats2half2_rn(ko[4*t + 0], ko[4*t + 1]);
        half2 k23 = __floats2half2_rn(ko[4*t + 2], ko[4*t + 3]);
        half2 v01 = __floats2half2_rn(vo[4*t + 0], vo[4*t + 1]);
        half2 v23 = __floats2half2_rn(vo[4*t + 2], vo[4*t + 3]);
        uint4 kvp;
        kvp.x = *reinterpret_cast<uint32_t*>(&k01);
        kvp.y = *reinterpret_cast<uint32_t*>(&k23);
        kvp.z = *reinterpret_cast<uint32_t*>(&v01);
        kvp.w = *reinterpret_cast<uint32_t*>(&v23);
        g_kv[(size_t)n * 32 + lane] = kvp;
    }
}

// histogram over idx_i + fused zeroing of the output buffer
__global__ void __launch_bounds__(256) hist_kernel(
    const int* __restrict__ idx_i,
    float4*    __restrict__ out4,
    int n4)
{
    int p = blockIdx.x * 256 + threadIdx.x;
    float4 z = make_float4(0.f, 0.f, 0.f, 0.f);
#pragma unroll
    for (int r = 0; r < 5; r++) {
        int o = p + r * N_PAIRS;
        if (o < n4) out4[o] = z;
    }
    if (p < N_PAIRS) atomicAdd(&g_cnt[idx_i[p]], 1);
}

// per-block (1024-element) exclusive scan of g_cnt into g_cursor; totals to g_bsum
__global__ void __launch_bounds__(256) scan1_kernel()
{
    __shared__ int sh[256];
    int t = threadIdx.x;
    int base = blockIdx.x * 1024 + t * 4;
    int v0 = (base + 0 < N_NODES) ? g_cnt[base + 0] : 0;
    int v1 = (base + 1 < N_NODES) ? g_cnt[base + 1] : 0;
    int v2 = (base + 2 < N_NODES) ? g_cnt[base + 2] : 0;
    int v3 = (base + 3 < N_NODES) ? g_cnt[base + 3] : 0;
    int s = v0 + v1 + v2 + v3;
    sh[t] = s;
    __syncthreads();
    for (int off = 1; off < 256; off <<= 1) {
        int add = (t >= off) ? sh[t - off] : 0;
        __syncthreads();
        sh[t] += add;
        __syncthreads();
    }
    int excl = sh[t] - s;
    if (base + 0 < N_NODES) g_cursor[base + 0] = excl;
    if (base + 1 < N_NODES) g_cursor[base + 1] = excl + v0;
    if (base + 2 < N_NODES) g_cursor[base + 2] = excl + v0 + v1;
    if (base + 3 < N_NODES) g_cursor[base + 3] = excl + v0 + v1 + v2;
    if (t == 255) g_bsum[blockIdx.x] = sh[255];
}

__global__ void __launch_bounds__(128) scan2_kernel()
{
    __shared__ int sh[128];
    int t = threadIdx.x;
    int v = (t < NB1) ? g_bsum[t] : 0;
    sh[t] = v;
    __syncthreads();
    for (int off = 1; off < 128; off <<= 1) {
        int add = (t >= off) ? sh[t - off] : 0;
        __syncthreads();
        sh[t] += add;
        __syncthreads();
    }
    if (t < NB1) g_bsum[t] = sh[t] - v;
}

// global slot = chunk-local cursor bump + chunk offset (scan3 folded in)
__global__ void __launch_bounds__(256) scatter_kernel(
    const int* __restrict__ idx_i,
    const int* __restrict__ idx_j,
    const float* __restrict__ phi)
{
    int p = blockIdx.x * 256 + threadIdx.x;
    if (p < N_PAIRS) {
        int i = idx_i[p];
        int pos = atomicAdd(&g_cursor[i], 1) + g_bsum[i >> 10];
        g_meta[pos] = make_int4(p, idx_j[p], __float_as_int(phi[p]), i);
    }
}

// Edge-parallel segmented reduction, two-pass warp body:
//   pass 1: all w/kv loads + alpha compute (no stores/asm -> full MLP batching)
//   pass 2: alpha*v accumulation with red.global flushes at segment boundaries
#define EDGES_PER_BLOCK 64
__global__ void __launch_bounds__(256) aggregate_kernel(
    const float* __restrict__ w_ij,
    float*       __restrict__ out)
{
    __shared__ int4 smeta[EDGES_PER_BLOCK];
    int t = threadIdx.x;
    int blockBase = blockIdx.x * EDGES_PER_BLOCK;
    if (t < EDGES_PER_BLOCK) smeta[t] = g_meta[blockBase + t];
    __syncthreads();

    int wid  = t >> 5;
    int lane = t & 31;
    int mbase = wid * 8;

    const float4* w4 = reinterpret_cast<const float4*>(w_ij);
    const float4* q4 = reinterpret_cast<const float4*>(g_q);

    // ---- pass 1: loads + alpha ----
    uint4 kv[8];
    float alpha[8];
    {
        int cur = smeta[mbase].w;
        float4 qc = __ldg(q4 + (size_t)cur * 32 + lane);
#pragma unroll
        for (int e = 0; e < 8; e++) {
            int4 mm = smeta[mbase + e];
            float4 we = __ldcs(w4 + (size_t)mm.x * 32 + lane);
            kv[e] = __ldg(&g_kv[(size_t)mm.y * 32 + lane]);
            if (mm.w != cur) {
                cur = mm.w;
                qc = __ldg(q4 + (size_t)cur * 32 + lane);
            }
            float2 k01 = __half22float2(*reinterpret_cast<half2*>(&kv[e].x));
            float2 k23 = __half22float2(*reinterpret_cast<half2*>(&kv[e].y));
            float part = qc.x * we.x * k01.x + qc.y * we.y * k01.y
                       + qc.z * we.z * k23.x + qc.w * we.w * k23.y;
            part += __shfl_xor_sync(0xFFFFFFFFu, part, 1);
            part += __shfl_xor_sync(0xFFFFFFFFu, part, 2);
            alpha[e] = part * 0.25f * __int_as_float(mm.z);   // 1/sqrt(16) * phi
        }
    }

    // ---- pass 2: segmented accumulate + flush ----
    {
        int cur = smeta[mbase].w;
        float4 acc = make_float4(0.f, 0.f, 0.f, 0.f);
#pragma unroll
        for (int e = 0; e < 8; e++) {
            int seg = smeta[mbase + e].w;
            if (seg != cur) {
                float* dst = out + (size_t)cur * F_TOTAL + lane * 4;
                asm volatile("red.global.add.v4.f32 [%0], {%1,%2,%3,%4};"
                             :: "l"(dst), "f"(acc.x), "f"(acc.y), "f"(acc.z), "f"(acc.w)
                             : "memory");
                cur = seg;
                acc = make_float4(0.f, 0.f, 0.f, 0.f);
            }
            float2 v01 = __half22float2(*reinterpret_cast<half2*>(&kv[e].z));
            float2 v23 = __half22float2(*reinterpret_cast<half2*>(&kv[e].w));
            acc.x += alpha[e] * v01.x;
            acc.y += alpha[e] * v01.y;
            acc.z += alpha[e] * v23.x;
            acc.w += alpha[e] * v23.y;
        }
        float* dst = out + (size_t)cur * F_TOTAL + lane * 4;
        asm volatile("red.global.add.v4.f32 [%0], {%1,%2,%3,%4};"
                     :: "l"(dst), "f"(acc.x), "f"(acc.y), "f"(acc.z), "f"(acc.w)
                     : "memory");
    }
}

extern "C" void kernel_launch(void* const* d_in, const int* in_sizes, int n_in,
                              void* d_out, int out_size)
{
    const float* x      = (const float*)d_in[0];
    const float* w_ij   = (const float*)d_in[1];
    const int*   idx_i  = (const int*)  d_in[2];
    const int*   idx_j  = (const int*)  d_in[3];
    const float* phi    = (const float*)d_in[4];
    const float* wq     = (const float*)d_in[5];
    const float* wk     = (const float*)d_in[6];
    const float* wv     = (const float*)d_in[7];
    float* out = (float*)d_out;

    proj_kernel<<<(N_NODES * N_HEADS + 255) / 256, 256>>>(x, wq, wk, wv);
    hist_kernel<<<(N_PAIRS + 255) / 256, 256>>>(idx_i, reinterpret_cast<float4*>(out), out_size / 4);
    scan1_kernel<<<NB1, 256>>>();
    scan2_kernel<<<1, 128>>>();
    scatter_kernel<<<(N_PAIRS + 255) / 256, 256>>>(idx_i, idx_j, phi);
    aggregate_kernel<<<N_PAIRS / EDGES_PER_BLOCK, 256>>>(w_ij, out);
}

// round 10
// speedup vs baseline: 1.1478x; 1.1478x over previous
#include <cuda_runtime.h>
#include <cuda_fp16.h>
#include <cstdint>

#define N_NODES 100000
#define N_PAIRS 640000
#define F_TOTAL 128
#define N_HEADS 8
#define HEAD_DIM 16

// projected q in (node, 128) fp32 layout.
// kv in fp16, interleaved per lane: node n, lane l -> uint4 = {k quad, v quad}.
__device__ float g_q[N_NODES * F_TOTAL];
__device__ uint4 g_kv[N_NODES * 32];

// CSR-by-idx_i machinery
__device__ int  g_cnt[N_NODES];      // zeroed inside proj_kernel each call
__device__ int  g_cursor[N_NODES];   // scan1 writes chunk-local exclusive prefix
__device__ int4 g_meta[N_PAIRS];     // {pair_id, idx_j, phi_bits, idx_i} grouped by idx_i
#define NB1 98                        // ceil(100000/1024)
__device__ int g_bsum[NB1];

#define W_STRIDE 260

__global__ void __launch_bounds__(256) proj_kernel(
    const float* __restrict__ x,
    const float* __restrict__ wq,
    const float* __restrict__ wk,
    const float* __restrict__ wv)
{
    __shared__ float sq[N_HEADS * W_STRIDE];
    __shared__ float sk[N_HEADS * W_STRIDE];
    __shared__ float sv[N_HEADS * W_STRIDE];

    int gid = blockIdx.x * 256 + threadIdx.x;   // node*8 + head
    if (gid < N_NODES) g_cnt[gid] = 0;          // fused zero_cnt

    for (int i = threadIdx.x; i < N_HEADS * HEAD_DIM * HEAD_DIM; i += 256) {
        int h = i >> 8;
        int r = i & 255;
        sq[h * W_STRIDE + r] = wq[i];
        sk[h * W_STRIDE + r] = wk[i];
        sv[h * W_STRIDE + r] = wv[i];
    }
    __syncthreads();

    if (gid >= N_NODES * N_HEADS) return;
    int n = gid >> 3;
    int h = gid & 7;

    const float4* xp = reinterpret_cast<const float4*>(x + (size_t)n * F_TOTAL + h * HEAD_DIM);
    float4 xv0 = xp[0], xv1 = xp[1], xv2 = xp[2], xv3 = xp[3];
    float xr[16] = {xv0.x, xv0.y, xv0.z, xv0.w,
                    xv1.x, xv1.y, xv1.z, xv1.w,
                    xv2.x, xv2.y, xv2.z, xv2.w,
                    xv3.x, xv3.y, xv3.z, xv3.w};

    const float4* wq4 = reinterpret_cast<const float4*>(sq + h * W_STRIDE);
    const float4* wk4 = reinterpret_cast<const float4*>(sk + h * W_STRIDE);
    const float4* wv4 = reinterpret_cast<const float4*>(sv + h * W_STRIDE);

    float qo[16], ko[16], vo[16];
#pragma unroll
    for (int e = 0; e < 16; e++) {
        float aq = 0.f, ak = 0.f, av = 0.f;
#pragma unroll
        for (int d4 = 0; d4 < 4; d4++) {
            float4 a = wq4[e * 4 + d4];
            float4 b = wk4[e * 4 + d4];
            float4 c = wv4[e * 4 + d4];
            float x0 = xr[4 * d4 + 0], x1 = xr[4 * d4 + 1];
            float x2 = xr[4 * d4 + 2], x3 = xr[4 * d4 + 3];
            aq += x0 * a.x + x1 * a.y + x2 * a.z + x3 * a.w;
            ak += x0 * b.x + x1 * b.y + x2 * b.z + x3 * b.w;
            av += x0 * c.x + x1 * c.y + x2 * c.z + x3 * c.w;
        }
        qo[e] = aq; ko[e] = ak; vo[e] = av;
    }

    float4* qdst = reinterpret_cast<float4*>(g_q + (size_t)n * F_TOTAL + h * HEAD_DIM);
#pragma unroll
    for (int t = 0; t < 4; t++) {
        qdst[t] = make_float4(qo[4*t], qo[4*t+1], qo[4*t+2], qo[4*t+3]);
        int lane = h * 4 + t;
        half2 k01 = __floats2half2_rn(ko[4*t + 0], ko[4*t + 1]);
        half2 k23 = __floats2half2_rn(ko[4*t + 2], ko[4*t + 3]);
        half2 v01 = __floats2half2_rn(vo[4*t + 0], vo[4*t + 1]);
        half2 v23 = __floats2half2_rn(vo[4*t + 2], vo[4*t + 3]);
        uint4 kvp;
        kvp.x = *reinterpret_cast<uint32_t*>(&k01);
        kvp.y = *reinterpret_cast<uint32_t*>(&k23);
        kvp.z = *reinterpret_cast<uint32_t*>(&v01);
        kvp.w = *reinterpret_cast<uint32_t*>(&v23);
        g_kv[(size_t)n * 32 + lane] = kvp;
    }
}

// histogram over idx_i + fused zeroing of the output buffer
__global__ void __launch_bounds__(256) hist_kernel(
    const int* __restrict__ idx_i,
    float4*    __restrict__ out4,
    int n4)
{
    int p = blockIdx.x * 256 + threadIdx.x;
    float4 z = make_float4(0.f, 0.f, 0.f, 0.f);
#pragma unroll
    for (int r = 0; r < 5; r++) {
        int o = p + r * N_PAIRS;
        if (o < n4) out4[o] = z;
    }
    if (p < N_PAIRS) atomicAdd(&g_cnt[idx_i[p]], 1);
}

// per-block (1024-element) exclusive scan of g_cnt into g_cursor; totals to g_bsum
__global__ void __launch_bounds__(256) scan1_kernel()
{
    __shared__ int sh[256];
    int t = threadIdx.x;
    int base = blockIdx.x * 1024 + t * 4;
    int v0 = (base + 0 < N_NODES) ? g_cnt[base + 0] : 0;
    int v1 = (base + 1 < N_NODES) ? g_cnt[base + 1] : 0;
    int v2 = (base + 2 < N_NODES) ? g_cnt[base + 2] : 0;
    int v3 = (base + 3 < N_NODES) ? g_cnt[base + 3] : 0;
    int s = v0 + v1 + v2 + v3;
    sh[t] = s;
    __syncthreads();
    for (int off = 1; off < 256; off <<= 1) {
        int add = (t >= off) ? sh[t - off] : 0;
        __syncthreads();
        sh[t] += add;
        __syncthreads();
    }
    int excl = sh[t] - s;
    if (base + 0 < N_NODES) g_cursor[base + 0] = excl;
    if (base + 1 < N_NODES) g_cursor[base + 1] = excl + v0;
    if (base + 2 < N_NODES) g_cursor[base + 2] = excl + v0 + v1;
    if (base + 3 < N_NODES) g_cursor[base + 3] = excl + v0 + v1 + v2;
    if (t == 255) g_bsum[blockIdx.x] = sh[255];
}

__global__ void __launch_bounds__(128) scan2_kernel()
{
    __shared__ int sh[128];
    int t = threadIdx.x;
    int v = (t < NB1) ? g_bsum[t] : 0;
    sh[t] = v;
    __syncthreads();
    for (int off = 1; off < 128; off <<= 1) {
        int add = (t >= off) ? sh[t - off] : 0;
        __syncthreads();
        sh[t] += add;
        __syncthreads();
    }
    if (t < NB1) g_bsum[t] = sh[t] - v;
}

// global slot = chunk-local cursor bump + chunk offset (scan3 folded in)
__global__ void __launch_bounds__(256) scatter_kernel(
    const int* __restrict__ idx_i,
    const int* __restrict__ idx_j,
    const float* __restrict__ phi)
{
    int p = blockIdx.x * 256 + threadIdx.x;
    if (p < N_PAIRS) {
        int i = idx_i[p];
        int pos = atomicAdd(&g_cursor[i], 1) + g_bsum[i >> 10];
        g_meta[pos] = make_int4(p, idx_j[p], __float_as_int(phi[p]), i);
    }
}

// Edge-parallel segmented reduction (round-8 structure: interleaved single
// pass, low register pressure). The red.global flushes carry NO memory
// clobber so ptxas may hoist later edges' loads above them.
#define EDGES_PER_BLOCK 64
__global__ void __launch_bounds__(256) aggregate_kernel(
    const float* __restrict__ w_ij,
    float*       __restrict__ out)
{
    __shared__ int4 smeta[EDGES_PER_BLOCK];
    int t = threadIdx.x;
    int blockBase = blockIdx.x * EDGES_PER_BLOCK;
    if (t < EDGES_PER_BLOCK) smeta[t] = g_meta[blockBase + t];
    __syncthreads();

    int wid  = t >> 5;
    int lane = t & 31;
    int mbase = wid * 8;

    const float4* w4 = reinterpret_cast<const float4*>(w_ij);
    const float4* q4 = reinterpret_cast<const float4*>(g_q);

    int cur = smeta[mbase].w;
    float4 qc = __ldg(q4 + (size_t)cur * 32 + lane);
    float4 acc = make_float4(0.f, 0.f, 0.f, 0.f);

#pragma unroll
    for (int e = 0; e < 8; e++) {
        int4 mm = smeta[mbase + e];                                  // LDS broadcast
        float4 we = __ldcs(w4 + (size_t)mm.x * 32 + lane);           // stream
        uint4 kve = __ldg(&g_kv[(size_t)mm.y * 32 + lane]);          // gather
        float phe = __int_as_float(mm.z);

        if (mm.w != cur) {                                           // segment boundary
            float* dst = out + (size_t)cur * F_TOTAL + lane * 4;
            asm volatile("red.global.add.v4.f32 [%0], {%1,%2,%3,%4};"
                         :: "l"(dst), "f"(acc.x), "f"(acc.y), "f"(acc.z), "f"(acc.w));
            cur = mm.w;
            qc = __ldg(q4 + (size_t)cur * 32 + lane);
            acc = make_float4(0.f, 0.f, 0.f, 0.f);
        }

        float2 k01 = __half22float2(*reinterpret_cast<half2*>(&kve.x));
        float2 k23 = __half22float2(*reinterpret_cast<half2*>(&kve.y));
        float2 v01 = __half22float2(*reinterpret_cast<half2*>(&kve.z));
        float2 v23 = __half22float2(*reinterpret_cast<half2*>(&kve.w));

        float part = qc.x * we.x * k01.x + qc.y * we.y * k01.y
                   + qc.z * we.z * k23.x + qc.w * we.w * k23.y;
        part += __shfl_xor_sync(0xFFFFFFFFu, part, 1);
        part += __shfl_xor_sync(0xFFFFFFFFu, part, 2);

        float alpha = part * 0.25f * phe;   // 1/sqrt(16)
        acc.x += alpha * v01.x;
        acc.y += alpha * v01.y;
        acc.z += alpha * v23.x;
        acc.w += alpha * v23.y;
    }
    float* dst = out + (size_t)cur * F_TOTAL + lane * 4;
    asm volatile("red.global.add.v4.f32 [%0], {%1,%2,%3,%4};"
                 :: "l"(dst), "f"(acc.x), "f"(acc.y), "f"(acc.z), "f"(acc.w));
}

extern "C" void kernel_launch(void* const* d_in, const int* in_sizes, int n_in,
                              void* d_out, int out_size)
{
    const float* x      = (const float*)d_in[0];
    const float* w_ij   = (const float*)d_in[1];
    const int*   idx_i  = (const int*)  d_in[2];
    const int*   idx_j  = (const int*)  d_in[3];
    const float* phi    = (const float*)d_in[4];
    const float* wq     = (const float*)d_in[5];
    const float* wk     = (const float*)d_in[6];
    const float* wv     = (const float*)d_in[7];
    float* out = (float*)d_out;

    proj_kernel<<<(N_NODES * N_HEADS + 255) / 256, 256>>>(x, wq, wk, wv);
    hist_kernel<<<(N_PAIRS + 255) / 256, 256>>>(idx_i, reinterpret_cast<float4*>(out), out_size / 4);
    scan1_kernel<<<NB1, 256>>>();
    scan2_kernel<<<1, 128>>>();
    scatter_kernel<<<(N_PAIRS + 255) / 256, 256>>>(idx_i, idx_j, phi);
    aggregate_kernel<<<N_PAIRS / EDGES_PER_BLOCK, 256>>>(w_ij, out);
}

// round 11
// speedup vs baseline: 1.2085x; 1.0529x over previous
#include <cuda_runtime.h>
#include <cuda_fp16.h>
#include <cstdint>

#define N_NODES 100000
#define N_PAIRS 640000
#define F_TOTAL 128
#define N_HEADS 8
#define HEAD_DIM 16

// q fp16: node n, lane l -> uint2 = q quad (features [4l,4l+4)) as 2x half2.
// kv fp16: node n, lane l -> uint4 = {k quad, v quad}.
__device__ uint2 g_qh[N_NODES * 32];
__device__ uint4 g_kv[N_NODES * 32];

// CSR-by-idx_i machinery
__device__ int  g_cnt[N_NODES];      // zeroed inside proj_kernel each call
__device__ int  g_cursor[N_NODES];   // scan1 writes chunk-local exclusive prefix
__device__ int4 g_meta[N_PAIRS];     // {pair_id, idx_j, phi_bits, idx_i} grouped by idx_i
#define NB1 98                        // ceil(100000/1024)
__device__ int g_bsum[NB1];           // raw per-chunk totals (scanned locally by scatter)

#define W_STRIDE 260

__global__ void __launch_bounds__(256) proj_kernel(
    const float* __restrict__ x,
    const float* __restrict__ wq,
    const float* __restrict__ wk,
    const float* __restrict__ wv)
{
    __shared__ float sq[N_HEADS * W_STRIDE];
    __shared__ float sk[N_HEADS * W_STRIDE];
    __shared__ float sv[N_HEADS * W_STRIDE];

    int gid = blockIdx.x * 256 + threadIdx.x;   // node*8 + head
    if (gid < N_NODES) g_cnt[gid] = 0;          // fused zero_cnt

    for (int i = threadIdx.x; i < N_HEADS * HEAD_DIM * HEAD_DIM; i += 256) {
        int h = i >> 8;
        int r = i & 255;
        sq[h * W_STRIDE + r] = wq[i];
        sk[h * W_STRIDE + r] = wk[i];
        sv[h * W_STRIDE + r] = wv[i];
    }
    __syncthreads();

    if (gid >= N_NODES * N_HEADS) return;
    int n = gid >> 3;
    int h = gid & 7;

    const float4* xp = reinterpret_cast<const float4*>(x + (size_t)n * F_TOTAL + h * HEAD_DIM);
    float4 xv0 = xp[0], xv1 = xp[1], xv2 = xp[2], xv3 = xp[3];
    float xr[16] = {xv0.x, xv0.y, xv0.z, xv0.w,
                    xv1.x, xv1.y, xv1.z, xv1.w,
                    xv2.x, xv2.y, xv2.z, xv2.w,
                    xv3.x, xv3.y, xv3.z, xv3.w};

    const float4* wq4 = reinterpret_cast<const float4*>(sq + h * W_STRIDE);
    const float4* wk4 = reinterpret_cast<const float4*>(sk + h * W_STRIDE);
    const float4* wv4 = reinterpret_cast<const float4*>(sv + h * W_STRIDE);

    float qo[16], ko[16], vo[16];
#pragma unroll
    for (int e = 0; e < 16; e++) {
        float aq = 0.f, ak = 0.f, av = 0.f;
#pragma unroll
        for (int d4 = 0; d4 < 4; d4++) {
            float4 a = wq4[e * 4 + d4];
            float4 b = wk4[e * 4 + d4];
            float4 c = wv4[e * 4 + d4];
            float x0 = xr[4 * d4 + 0], x1 = xr[4 * d4 + 1];
            float x2 = xr[4 * d4 + 2], x3 = xr[4 * d4 + 3];
            aq += x0 * a.x + x1 * a.y + x2 * a.z + x3 * a.w;
            ak += x0 * b.x + x1 * b.y + x2 * b.z + x3 * b.w;
            av += x0 * c.x + x1 * c.y + x2 * c.z + x3 * c.w;
        }
        qo[e] = aq; ko[e] = ak; vo[e] = av;
    }

#pragma unroll
    for (int t = 0; t < 4; t++) {
        int lane = h * 4 + t;
        half2 q01 = __floats2half2_rn(qo[4*t + 0], qo[4*t + 1]);
        half2 q23 = __floats2half2_rn(qo[4*t + 2], qo[4*t + 3]);
        uint2 qp;
        qp.x = *reinterpret_cast<uint32_t*>(&q01);
        qp.y = *reinterpret_cast<uint32_t*>(&q23);
        g_qh[(size_t)n * 32 + lane] = qp;

        half2 k01 = __floats2half2_rn(ko[4*t + 0], ko[4*t + 1]);
        half2 k23 = __floats2half2_rn(ko[4*t + 2], ko[4*t + 3]);
        half2 v01 = __floats2half2_rn(vo[4*t + 0], vo[4*t + 1]);
        half2 v23 = __floats2half2_rn(vo[4*t + 2], vo[4*t + 3]);
        uint4 kvp;
        kvp.x = *reinterpret_cast<uint32_t*>(&k01);
        kvp.y = *reinterpret_cast<uint32_t*>(&k23);
        kvp.z = *reinterpret_cast<uint32_t*>(&v01);
        kvp.w = *reinterpret_cast<uint32_t*>(&v23);
        g_kv[(size_t)n * 32 + lane] = kvp;
    }
}

// histogram over idx_i + fused zeroing of the output buffer
__global__ void __launch_bounds__(256) hist_kernel(
    const int* __restrict__ idx_i,
    float4*    __restrict__ out4,
    int n4)
{
    int p = blockIdx.x * 256 + threadIdx.x;
    float4 z = make_float4(0.f, 0.f, 0.f, 0.f);
#pragma unroll
    for (int r = 0; r < 5; r++) {
        int o = p + r * N_PAIRS;
        if (o < n4) out4[o] = z;
    }
    if (p < N_PAIRS) atomicAdd(&g_cnt[idx_i[p]], 1);
}

// per-block (1024-element) exclusive scan of g_cnt into g_cursor; raw totals to g_bsum
__global__ void __launch_bounds__(256) scan1_kernel()
{
    __shared__ int sh[256];
    int t = threadIdx.x;
    int base = blockIdx.x * 1024 + t * 4;
    int v0 = (base + 0 < N_NODES) ? g_cnt[base + 0] : 0;
    int v1 = (base + 1 < N_NODES) ? g_cnt[base + 1] : 0;
    int v2 = (base + 2 < N_NODES) ? g_cnt[base + 2] : 0;
    int v3 = (base + 3 < N_NODES) ? g_cnt[base + 3] : 0;
    int s = v0 + v1 + v2 + v3;
    sh[t] = s;
    __syncthreads();
    for (int off = 1; off < 256; off <<= 1) {
        int add = (t >= off) ? sh[t - off] : 0;
        __syncthreads();
        sh[t] += add;
        __syncthreads();
    }
    int excl = sh[t] - s;
    if (base + 0 < N_NODES) g_cursor[base + 0] = excl;
    if (base + 1 < N_NODES) g_cursor[base + 1] = excl + v0;
    if (base + 2 < N_NODES) g_cursor[base + 2] = excl + v0 + v1;
    if (base + 3 < N_NODES) g_cursor[base + 3] = excl + v0 + v1 + v2;
    if (t == 255) g_bsum[blockIdx.x] = sh[255];
}

// scatter with the 98-entry chunk-offset scan done redundantly per block
// (removes the scan2 launch). slot = local cursor bump + scanned chunk offset.
__global__ void __launch_bounds__(256) scatter_kernel(
    const int* __restrict__ idx_i,
    const int* __restrict__ idx_j,
    const float* __restrict__ phi)
{
    __shared__ int sh[128];
    __shared__ int sexcl[128];
    int t = threadIdx.x;

    int v = 0;
    if (t < 128) {
        v = (t < NB1) ? g_bsum[t] : 0;
        sh[t] = v;
    }
    __syncthreads();
    for (int off = 1; off < 128; off <<= 1) {
        int add = 0;
        if (t < 128 && t >= off) add = sh[t - off];
        __syncthreads();
        if (t < 128) sh[t] += add;
        __syncthreads();
    }
    if (t < 128) sexcl[t] = sh[t] - v;
    __syncthreads();

    int p = blockIdx.x * 256 + t;
    if (p < N_PAIRS) {
        int i = idx_i[p];
        int pos = atomicAdd(&g_cursor[i], 1) + sexcl[i >> 10];
        g_meta[pos] = make_int4(p, idx_j[p], __float_as_int(phi[p]), i);
    }
}

// Edge-parallel segmented reduction: 512-thread blocks, 16 warps x 8 edges.
// Interleaved single-pass body (low regs); red.global flushes carry no memory
// clobber so ptxas may hoist later edges' loads above them.
#define EDGES_PER_BLOCK 128
__global__ void __launch_bounds__(512) aggregate_kernel(
    const float* __restrict__ w_ij,
    float*       __restrict__ out)
{
    __shared__ int4 smeta[EDGES_PER_BLOCK];
    int t = threadIdx.x;
    int blockBase = blockIdx.x * EDGES_PER_BLOCK;
    if (t < EDGES_PER_BLOCK) smeta[t] = g_meta[blockBase + t];
    __syncthreads();

    int wid  = t >> 5;
    int lane = t & 31;
    int mbase = wid * 8;

    const float4* w4 = reinterpret_cast<const float4*>(w_ij);

    int cur = smeta[mbase].w;
    uint2 qp = __ldg(&g_qh[(size_t)cur * 32 + lane]);
    float2 q01 = __half22float2(*reinterpret_cast<half2*>(&qp.x));
    float2 q23 = __half22float2(*reinterpret_cast<half2*>(&qp.y));
    float4 acc = make_float4(0.f, 0.f, 0.f, 0.f);

#pragma unroll
    for (int e = 0; e < 8; e++) {
        int4 mm = smeta[mbase + e];                                  // LDS broadcast
        float4 we = __ldcs(w4 + (size_t)mm.x * 32 + lane);           // stream
        uint4 kve = __ldg(&g_kv[(size_t)mm.y * 32 + lane]);          // gather
        float phe = __int_as_float(mm.z);

        if (mm.w != cur) {                                           // segment boundary
            float* dst = out + (size_t)cur * F_TOTAL + lane * 4;
            asm volatile("red.global.add.v4.f32 [%0], {%1,%2,%3,%4};"
                         :: "l"(dst), "f"(acc.x), "f"(acc.y), "f"(acc.z), "f"(acc.w));
            cur = mm.w;
            qp = __ldg(&g_qh[(size_t)cur * 32 + lane]);
            q01 = __half22float2(*reinterpret_cast<half2*>(&qp.x));
            q23 = __half22float2(*reinterpret_cast<half2*>(&qp.y));
            acc = make_float4(0.f, 0.f, 0.f, 0.f);
        }

        float2 k01 = __half22float2(*reinterpret_cast<half2*>(&kve.x));
        float2 k23 = __half22float2(*reinterpret_cast<half2*>(&kve.y));
        float2 v01 = __half22float2(*reinterpret_cast<half2*>(&kve.z));
        float2 v23 = __half22float2(*reinterpret_cast<half2*>(&kve.w));

        float part = q01.x * we.x * k01.x + q01.y * we.y * k01.y
                   + q23.x * we.z * k23.x + q23.y * we.w * k23.y;
        part += __shfl_xor_sync(0xFFFFFFFFu, part, 1);
        part += __shfl_xor_sync(0xFFFFFFFFu, part, 2);

        float alpha = part * 0.25f * phe;   // 1/sqrt(16)
        acc.x += alpha * v01.x;
        acc.y += alpha * v01.y;
        acc.z += alpha * v23.x;
        acc.w += alpha * v23.y;
    }
    float* dst = out + (size_t)cur * F_TOTAL + lane * 4;
    asm volatile("red.global.add.v4.f32 [%0], {%1,%2,%3,%4};"
                 :: "l"(dst), "f"(acc.x), "f"(acc.y), "f"(acc.z), "f"(acc.w));
}

extern "C" void kernel_launch(void* const* d_in, const int* in_sizes, int n_in,
                              void* d_out, int out_size)
{
    const float* x      = (const float*)d_in[0];
    const float* w_ij   = (const float*)d_in[1];
    const int*   idx_i  = (const int*)  d_in[2];
    const int*   idx_j  = (const int*)  d_in[3];
    const float* phi    = (const float*)d_in[4];
    const float* wq     = (const float*)d_in[5];
    const float* wk     = (const float*)d_in[6];
    const float* wv     = (const float*)d_in[7];
    float* out = (float*)d_out;

    proj_kernel<<<(N_NODES * N_HEADS + 255) / 256, 256>>>(x, wq, wk, wv);
    hist_kernel<<<(N_PAIRS + 255) / 256, 256>>>(idx_i, reinterpret_cast<float4*>(out), out_size / 4);
    scan1_kernel<<<NB1, 256>>>();
    scatter_kernel<<<(N_PAIRS + 255) / 256, 256>>>(idx_i, idx_j, phi);
    aggregate_kernel<<<N_PAIRS / EDGES_PER_BLOCK, 512>>>(w_ij, out);
}

// round 12
// speedup vs baseline: 1.2311x; 1.0186x over previous
#include <cuda_runtime.h>
#include <cuda_fp16.h>
#include <cstdint>

#define N_NODES 100000
#define N_PAIRS 640000
#define F_TOTAL 128
#define N_HEADS 8
#define HEAD_DIM 16

// q fp16: node n, lane l -> uint2 = q quad (features [4l,4l+4)) as 2x half2.
// kv fp16: node n, lane l -> uint4 = {k quad, v quad}.
__device__ uint2 g_qh[N_NODES * 32];
__device__ uint4 g_kv[N_NODES * 32];

// CSR-by-idx_i machinery
__device__ int  g_cnt[N_NODES];      // zeroed inside proj_kernel each call
__device__ int  g_cursor[N_NODES];   // scan1 writes chunk-local exclusive prefix
__device__ int4 g_meta[N_PAIRS];     // {pair_id, idx_j, phi_bits, idx_i} grouped by idx_i
#define NB1 98                        // ceil(100000/1024)
__device__ int g_bsum[NB1];           // raw per-chunk totals (scanned locally by scatter)

#define W_STRIDE 260

__global__ void __launch_bounds__(256) proj_kernel(
    const float* __restrict__ x,
    const float* __restrict__ wq,
    const float* __restrict__ wk,
    const float* __restrict__ wv)
{
    __shared__ float sq[N_HEADS * W_STRIDE];
    __shared__ float sk[N_HEADS * W_STRIDE];
    __shared__ float sv[N_HEADS * W_STRIDE];

    int gid = blockIdx.x * 256 + threadIdx.x;   // node*8 + head
    if (gid < N_NODES) g_cnt[gid] = 0;          // fused zero_cnt

    for (int i = threadIdx.x; i < N_HEADS * HEAD_DIM * HEAD_DIM; i += 256) {
        int h = i >> 8;
        int r = i & 255;
        sq[h * W_STRIDE + r] = wq[i];
        sk[h * W_STRIDE + r] = wk[i];
        sv[h * W_STRIDE + r] = wv[i];
    }
    __syncthreads();

    if (gid >= N_NODES * N_HEADS) return;
    int n = gid >> 3;
    int h = gid & 7;

    const float4* xp = reinterpret_cast<const float4*>(x + (size_t)n * F_TOTAL + h * HEAD_DIM);
    float4 xv0 = xp[0], xv1 = xp[1], xv2 = xp[2], xv3 = xp[3];
    float xr[16] = {xv0.x, xv0.y, xv0.z, xv0.w,
                    xv1.x, xv1.y, xv1.z, xv1.w,
                    xv2.x, xv2.y, xv2.z, xv2.w,
                    xv3.x, xv3.y, xv3.z, xv3.w};

    const float4* wq4 = reinterpret_cast<const float4*>(sq + h * W_STRIDE);
    const float4* wk4 = reinterpret_cast<const float4*>(sk + h * W_STRIDE);
    const float4* wv4 = reinterpret_cast<const float4*>(sv + h * W_STRIDE);

    float qo[16], ko[16], vo[16];
#pragma unroll
    for (int e = 0; e < 16; e++) {
        float aq = 0.f, ak = 0.f, av = 0.f;
#pragma unroll
        for (int d4 = 0; d4 < 4; d4++) {
            float4 a = wq4[e * 4 + d4];
            float4 b = wk4[e * 4 + d4];
            float4 c = wv4[e * 4 + d4];
            float x0 = xr[4 * d4 + 0], x1 = xr[4 * d4 + 1];
            float x2 = xr[4 * d4 + 2], x3 = xr[4 * d4 + 3];
            aq += x0 * a.x + x1 * a.y + x2 * a.z + x3 * a.w;
            ak += x0 * b.x + x1 * b.y + x2 * b.z + x3 * b.w;
            av += x0 * c.x + x1 * c.y + x2 * c.z + x3 * c.w;
        }
        qo[e] = aq; ko[e] = ak; vo[e] = av;
    }

#pragma unroll
    for (int t = 0; t < 4; t++) {
        int lane = h * 4 + t;
        half2 q01 = __floats2half2_rn(qo[4*t + 0], qo[4*t + 1]);
        half2 q23 = __floats2half2_rn(qo[4*t + 2], qo[4*t + 3]);
        uint2 qp;
        qp.x = *reinterpret_cast<uint32_t*>(&q01);
        qp.y = *reinterpret_cast<uint32_t*>(&q23);
        g_qh[(size_t)n * 32 + lane] = qp;

        half2 k01 = __floats2half2_rn(ko[4*t + 0], ko[4*t + 1]);
        half2 k23 = __floats2half2_rn(ko[4*t + 2], ko[4*t + 3]);
        half2 v01 = __floats2half2_rn(vo[4*t + 0], vo[4*t + 1]);
        half2 v23 = __floats2half2_rn(vo[4*t + 2], vo[4*t + 3]);
        uint4 kvp;
        kvp.x = *reinterpret_cast<uint32_t*>(&k01);
        kvp.y = *reinterpret_cast<uint32_t*>(&k23);
        kvp.z = *reinterpret_cast<uint32_t*>(&v01);
        kvp.w = *reinterpret_cast<uint32_t*>(&v23);
        g_kv[(size_t)n * 32 + lane] = kvp;
    }
}

// histogram over idx_i + fused zeroing of the output buffer
__global__ void __launch_bounds__(256) hist_kernel(
    const int* __restrict__ idx_i,
    float4*    __restrict__ out4,
    int n4)
{
    int p = blockIdx.x * 256 + threadIdx.x;
    float4 z = make_float4(0.f, 0.f, 0.f, 0.f);
#pragma unroll
    for (int r = 0; r < 5; r++) {
        int o = p + r * N_PAIRS;
        if (o < n4) out4[o] = z;
    }
    if (p < N_PAIRS) atomicAdd(&g_cnt[idx_i[p]], 1);
}

// per-block (1024-element) exclusive scan of g_cnt into g_cursor; raw totals to g_bsum
__global__ void __launch_bounds__(256) scan1_kernel()
{
    __shared__ int sh[256];
    int t = threadIdx.x;
    int base = blockIdx.x * 1024 + t * 4;
    int v0 = (base + 0 < N_NODES) ? g_cnt[base + 0] : 0;
    int v1 = (base + 1 < N_NODES) ? g_cnt[base + 1] : 0;
    int v2 = (base + 2 < N_NODES) ? g_cnt[base + 2] : 0;
    int v3 = (base + 3 < N_NODES) ? g_cnt[base + 3] : 0;
    int s = v0 + v1 + v2 + v3;
    sh[t] = s;
    __syncthreads();
    for (int off = 1; off < 256; off <<= 1) {
        int add = (t >= off) ? sh[t - off] : 0;
        __syncthreads();
        sh[t] += add;
        __syncthreads();
    }
    int excl = sh[t] - s;
    if (base + 0 < N_NODES) g_cursor[base + 0] = excl;
    if (base + 1 < N_NODES) g_cursor[base + 1] = excl + v0;
    if (base + 2 < N_NODES) g_cursor[base + 2] = excl + v0 + v1;
    if (base + 3 < N_NODES) g_cursor[base + 3] = excl + v0 + v1 + v2;
    if (t == 255) g_bsum[blockIdx.x] = sh[255];
}

// scatter with the 98-entry chunk-offset scan done redundantly per block
// (no scan2 launch). slot = local cursor bump + scanned chunk offset.
__global__ void __launch_bounds__(256) scatter_kernel(
    const int* __restrict__ idx_i,
    const int* __restrict__ idx_j,
    const float* __restrict__ phi)
{
    __shared__ int sh[128];
    __shared__ int sexcl[128];
    int t = threadIdx.x;

    int v = 0;
    if (t < 128) {
        v = (t < NB1) ? g_bsum[t] : 0;
        sh[t] = v;
    }
    __syncthreads();
    for (int off = 1; off < 128; off <<= 1) {
        int add = 0;
        if (t < 128 && t >= off) add = sh[t - off];
        __syncthreads();
        if (t < 128) sh[t] += add;
        __syncthreads();
    }
    if (t < 128) sexcl[t] = sh[t] - v;
    __syncthreads();

    int p = blockIdx.x * 256 + t;
    if (p < N_PAIRS) {
        int i = idx_i[p];
        int pos = atomicAdd(&g_cursor[i], 1) + sexcl[i >> 10];
        g_meta[pos] = make_int4(p, idx_j[p], __float_as_int(phi[p]), i);
    }
}

// Edge-parallel segmented reduction. Each warp owns 16 edges, stages its own
// metas (256B coalesced) into a private smem slice, syncs with __syncwarp only
// (no block coupling), then runs the interleaved single-pass body. red.global
// flushes carry no memory clobber so later loads can hoist above them.
#define EDGES_PER_WARP 16
#define WARPS_PER_BLOCK 8
#define EDGES_PER_BLOCK (EDGES_PER_WARP * WARPS_PER_BLOCK)
__global__ void __launch_bounds__(256) aggregate_kernel(
    const float* __restrict__ w_ij,
    float*       __restrict__ out)
{
    __shared__ int4 smeta[EDGES_PER_BLOCK];
    int t = threadIdx.x;
    int wid  = t >> 5;
    int lane = t & 31;
    int mbase = wid * EDGES_PER_WARP;
    int warpBase = blockIdx.x * EDGES_PER_BLOCK + mbase;

    if (lane < EDGES_PER_WARP) smeta[mbase + lane] = g_meta[warpBase + lane];
    __syncwarp();

    const float4* w4 = reinterpret_cast<const float4*>(w_ij);

    int cur = smeta[mbase].w;
    uint2 qp = __ldg(&g_qh[(size_t)cur * 32 + lane]);
    float2 q01 = __half22float2(*reinterpret_cast<half2*>(&qp.x));
    float2 q23 = __half22float2(*reinterpret_cast<half2*>(&qp.y));
    float4 acc = make_float4(0.f, 0.f, 0.f, 0.f);

#pragma unroll
    for (int e = 0; e < EDGES_PER_WARP; e++) {
        int4 mm = smeta[mbase + e];                                  // LDS broadcast
        float4 we = __ldcs(w4 + (size_t)mm.x * 32 + lane);           // stream
        uint4 kve = __ldg(&g_kv[(size_t)mm.y * 32 + lane]);          // gather
        float phe = __int_as_float(mm.z);

        if (mm.w != cur) {                                           // segment boundary
            float* dst = out + (size_t)cur * F_TOTAL + lane * 4;
            asm volatile("red.global.add.v4.f32 [%0], {%1,%2,%3,%4};"
                         :: "l"(dst), "f"(acc.x), "f"(acc.y), "f"(acc.z), "f"(acc.w));
            cur = mm.w;
            qp = __ldg(&g_qh[(size_t)cur * 32 + lane]);
            q01 = __half22float2(*reinterpret_cast<half2*>(&qp.x));
            q23 = __half22float2(*reinterpret_cast<half2*>(&qp.y));
            acc = make_float4(0.f, 0.f, 0.f, 0.f);
        }

        float2 k01 = __half22float2(*reinterpret_cast<half2*>(&kve.x));
        float2 k23 = __half22float2(*reinterpret_cast<half2*>(&kve.y));
        float2 v01 = __half22float2(*reinterpret_cast<half2*>(&kve.z));
        float2 v23 = __half22float2(*reinterpret_cast<half2*>(&kve.w));

        float part = q01.x * we.x * k01.x + q01.y * we.y * k01.y
                   + q23.x * we.z * k23.x + q23.y * we.w * k23.y;
        part += __shfl_xor_sync(0xFFFFFFFFu, part, 1);
        part += __shfl_xor_sync(0xFFFFFFFFu, part, 2);

        float alpha = part * 0.25f * phe;   // 1/sqrt(16)
        acc.x += alpha * v01.x;
        acc.y += alpha * v01.y;
        acc.z += alpha * v23.x;
        acc.w += alpha * v23.y;
    }
    float* dst = out + (size_t)cur * F_TOTAL + lane * 4;
    asm volatile("red.global.add.v4.f32 [%0], {%1,%2,%3,%4};"
                 :: "l"(dst), "f"(acc.x), "f"(acc.y), "f"(acc.z), "f"(acc.w));
}

extern "C" void kernel_launch(void* const* d_in, const int* in_sizes, int n_in,
                              void* d_out, int out_size)
{
    const float* x      = (const float*)d_in[0];
    const float* w_ij   = (const float*)d_in[1];
    const int*   idx_i  = (const int*)  d_in[2];
    const int*   idx_j  = (const int*)  d_in[3];
    const float* phi    = (const float*)d_in[4];
    const float* wq     = (const float*)d_in[5];
    const float* wk     = (const float*)d_in[6];
    const float* wv     = (const float*)d_in[7];
    float* out = (float*)d_out;

    proj_kernel<<<(N_NODES * N_HEADS + 255) / 256, 256>>>(x, wq, wk, wv);
    hist_kernel<<<(N_PAIRS + 255) / 256, 256>>>(idx_i, reinterpret_cast<float4*>(out), out_size / 4);
    scan1_kernel<<<NB1, 256>>>();
    scatter_kernel<<<(N_PAIRS + 255) / 256, 256>>>(idx_i, idx_j, phi);
    aggregate_kernel<<<N_PAIRS / EDGES_PER_BLOCK, 256>>>(w_ij, out);
}